// round 1
// baseline (speedup 1.0000x reference)
#include <cuda_runtime.h>
#include <cstdint>

#define COLS   24576
#define KSEL   64
#define NT     512
#define VEC    (COLS / 4 / NT)     // 12 float4 per thread
#define CAP    3840                // candidate capacity (expected ~560 at cut=2.0)
#define SMEM_BYTES ((COLS + CAP + 256) * 4)   // 114688 B -> 2 CTAs/SM

// Monotonic float -> uint32 mapping (order-preserving)
__device__ __forceinline__ uint32_t f2s(float f) {
    uint32_t b = __float_as_uint(f);
    return (b & 0x80000000u) ? ~b : (b | 0x80000000u);
}
__device__ __forceinline__ float s2f(uint32_t u) {
    uint32_t b = (u & 0x80000000u) ? (u ^ 0x80000000u) : ~u;
    return __uint_as_float(b);
}

// Warp-aggregated candidate push: one shared atomic per warp per visit.
__device__ __forceinline__ void push_cand(uint32_t u, uint32_t cut,
                                          uint32_t* cand, int* cnt, int lane) {
    bool p = u > cut;
    unsigned m = __ballot_sync(0xFFFFFFFFu, p);
    if (m) {
        int leader = __ffs(m) - 1;
        int base = 0;
        if (lane == leader) base = atomicAdd(cnt, __popc(m));
        base = __shfl_sync(0xFFFFFFFFu, base, leader);
        if (p) {
            int pos = base + __popc(m & ((1u << lane) - 1u));
            if (pos < CAP) cand[pos] = u;
        }
    }
}

__global__ __launch_bounds__(NT, 2)
void topk_relu_scatter(const float* __restrict__ x, float* __restrict__ out) {
    extern __shared__ uint32_t smem[];
    uint32_t* srow = smem;                    // COLS sortable uints (row cache)
    uint32_t* cand = smem + COLS;             // CAP candidates
    uint32_t* hist = smem + COLS + CAP;       // 256-bin radix histogram
    __shared__ int sCnt, sKth, sEq;
    __shared__ uint32_t sPrefix;

    const int tid  = threadIdx.x;
    const int lane = tid & 31;
    const long long row = blockIdx.x;

    if (tid == 0) { sCnt = 0; sEq = 0; sKth = KSEL; sPrefix = 0u; }
    __syncthreads();

    const float4* __restrict__ rowv = reinterpret_cast<const float4*>(x + row * (long long)COLS);
    uint4* srowv = reinterpret_cast<uint4*>(srow);

    // ---- Phase 1: streaming load, convert to sortable, cache in SMEM,
    //               extract candidates above a safe cutoff (2.0) ----
    uint32_t cut = f2s(2.0f);
#pragma unroll
    for (int j = 0; j < VEC; j++) {
        int i = j * NT + tid;
        float4 f = __ldcs(rowv + i);
        uint4 u;
        u.x = f2s(f.x); u.y = f2s(f.y); u.z = f2s(f.z); u.w = f2s(f.w);
        srowv[i] = u;
        push_cand(u.x, cut, cand, &sCnt, lane);
        push_cand(u.y, cut, cand, &sCnt, lane);
        push_cand(u.z, cut, cand, &sCnt, lane);
        push_cand(u.w, cut, cand, &sCnt, lane);
    }
    __syncthreads();
    int cnt = min(sCnt, CAP);

    // Uniform fallback if the row had < K values above 2.0 (not expected for N(0,1))
    if (cnt < KSEL) {
        __syncthreads();
        if (tid == 0) sCnt = 0;
        __syncthreads();
        cut = f2s(1.25f);   // ~2600 expected candidates, fits CAP
#pragma unroll
        for (int j = 0; j < VEC; j++) {
            int i = j * NT + tid;
            uint4 u = srowv[i];
            push_cand(u.x, cut, cand, &sCnt, lane);
            push_cand(u.y, cut, cand, &sCnt, lane);
            push_cand(u.z, cut, cand, &sCnt, lane);
            push_cand(u.w, cut, cand, &sCnt, lane);
        }
        __syncthreads();
        cnt = min(sCnt, CAP);
    }

    // ---- Phase 2: 4x8-bit radix select for K-th largest among candidates ----
#pragma unroll
    for (int pass = 0; pass < 4; pass++) {
        const int shift = 24 - 8 * pass;
        const uint32_t pmask = (pass == 0) ? 0u : (0xFFFFFFFFu << (shift + 8));
        if (tid < 256) hist[tid] = 0;
        __syncthreads();                         // also publishes prior sPrefix/sKth
        const uint32_t prefix = sPrefix;
        const int kth = sKth;
        for (int i = tid; i < cnt; i += NT) {
            uint32_t u = cand[i];
            if ((u & pmask) == prefix) atomicAdd(&hist[(u >> shift) & 0xFFu], 1);
        }
        __syncthreads();
        if (tid < 32) {                          // warp-0 suffix scan of 256 bins
            const int b0 = lane * 8;
            int s[9];
            s[8] = 0;
            int run = 0;
#pragma unroll
            for (int i = 7; i >= 0; i--) { run += (int)hist[b0 + i]; s[i] = run; }
            int incl = run;
#pragma unroll
            for (int off = 1; off < 32; off <<= 1) {
                int v = __shfl_down_sync(0xFFFFFFFFu, incl, off);
                if (lane + off < 32) incl += v;
            }
            int excl = __shfl_down_sync(0xFFFFFFFFu, incl, 1);
            if (lane == 31) excl = 0;
#pragma unroll
            for (int i = 0; i < 8; i++) {
                int suf = s[i] + excl;           // count of candidates >= bin b0+i
                int nxt = s[i + 1] + excl;       // count strictly above this bin
                if (suf >= kth && nxt < kth) {   // unique bin
                    sPrefix = prefix | ((uint32_t)(b0 + i) << shift);
                    sKth = kth - nxt;            // remaining rank among equals
                }
            }
        }
        __syncthreads();
    }

    const uint32_t T = sPrefix;                  // exact 64th-largest sortable uint
    const int eqAllow = sKth;                    // # of ties at T to accept (>=1)
    float4* __restrict__ outv = reinterpret_cast<float4*>(out + row * (long long)COLS);

    // ---- Phase 3: streaming output pass from SMEM ----
#pragma unroll
    for (int j = 0; j < VEC; j++) {
        int i = j * NT + tid;
        uint4 u = srowv[i];
        float4 o = make_float4(0.f, 0.f, 0.f, 0.f);
        if (u.x >= T) {
            if (u.x > T) o.x = fmaxf(s2f(u.x), 0.f);
            else if (atomicAdd(&sEq, 1) < eqAllow) o.x = fmaxf(s2f(u.x), 0.f);
        }
        if (u.y >= T) {
            if (u.y > T) o.y = fmaxf(s2f(u.y), 0.f);
            else if (atomicAdd(&sEq, 1) < eqAllow) o.y = fmaxf(s2f(u.y), 0.f);
        }
        if (u.z >= T) {
            if (u.z > T) o.z = fmaxf(s2f(u.z), 0.f);
            else if (atomicAdd(&sEq, 1) < eqAllow) o.z = fmaxf(s2f(u.z), 0.f);
        }
        if (u.w >= T) {
            if (u.w > T) o.w = fmaxf(s2f(u.w), 0.f);
            else if (atomicAdd(&sEq, 1) < eqAllow) o.w = fmaxf(s2f(u.w), 0.f);
        }
        __stcs(outv + i, o);
    }
}

extern "C" void kernel_launch(void* const* d_in, const int* in_sizes, int n_in,
                              void* d_out, int out_size) {
    const float* x = (const float*)d_in[0];
    float* out = (float*)d_out;
    int rows = in_sizes[0] / COLS;

    cudaFuncSetAttribute(topk_relu_scatter,
                         cudaFuncAttributeMaxDynamicSharedMemorySize, SMEM_BYTES);
    topk_relu_scatter<<<rows, NT, SMEM_BYTES>>>(x, out);
}

// round 4
// speedup vs baseline: 1.2127x; 1.2127x over previous
#include <cuda_runtime.h>
#include <cstdint>

#define COLS   24576
#define KSEL   64
#define NT     512
#define VEC    (COLS / 4 / NT)     // 12 float4 per thread
#define CAP    3840                // candidate capacity (expected ~560 at cut=2.0)
#define SMEM_BYTES ((COLS + CAP + 256) * 4)   // 114688 B -> 2 CTAs/SM

// Monotonic float -> uint32 mapping (order-preserving), used ONLY on candidates.
__device__ __forceinline__ uint32_t f2s(float f) {
    uint32_t b = __float_as_uint(f);
    return (b & 0x80000000u) ? ~b : (b | 0x80000000u);
}
__device__ __forceinline__ float s2f(uint32_t u) {
    uint32_t b = (u & 0x80000000u) ? (u ^ 0x80000000u) : ~u;
    return __uint_as_float(b);
}

__global__ __launch_bounds__(NT, 2)
void topk_relu_scatter(const float* __restrict__ x, float* __restrict__ out) {
    extern __shared__ uint32_t smem[];
    float4*   srow = (float4*)smem;           // COLS raw floats (row cache), as float4
    uint32_t* cand = smem + COLS;             // CAP sortable candidate bits
    uint32_t* hist = smem + COLS + CAP;       // 256-bin radix histogram
    __shared__ int sCnt, sKth, sEq;
    __shared__ uint32_t sPrefix;

    const int tid = threadIdx.x;
    const long long row = blockIdx.x;

    if (tid == 0) { sCnt = 0; sEq = 0; sKth = KSEL; sPrefix = 0u; }
    __syncthreads();

    const float4* __restrict__ rowv = (const float4*)(x + row * (long long)COLS);
    float4* __restrict__ outv = (float4*)(out + row * (long long)COLS);

    // ---- Phase 1: streaming load -> raw SMEM cache; rare-path candidate push ----
    float cutf = 2.0f;
#pragma unroll
    for (int j = 0; j < VEC; j++) {
        const int i = j * NT + tid;
        float4 f = __ldcs(rowv + i);
        srow[i] = f;
        if (f.x > cutf) { int p = atomicAdd(&sCnt, 1); if (p < CAP) cand[p] = f2s(f.x); }
        if (f.y > cutf) { int p = atomicAdd(&sCnt, 1); if (p < CAP) cand[p] = f2s(f.y); }
        if (f.z > cutf) { int p = atomicAdd(&sCnt, 1); if (p < CAP) cand[p] = f2s(f.z); }
        if (f.w > cutf) { int p = atomicAdd(&sCnt, 1); if (p < CAP) cand[p] = f2s(f.w); }
    }
    __syncthreads();
    int cnt = sCnt;

    // ---- Robustness fallback (never taken for N(0,1) rows; refilter from SMEM) ----
    if (cnt > CAP || cnt < KSEL) {
        cutf = (cnt < KSEL) ? 0.0f : 3.0f;   // ReLU makes cut=0.0 fully general
        __syncthreads();
        if (tid == 0) sCnt = 0;
        __syncthreads();
        for (int j = 0; j < VEC; j++) {
            const int i = j * NT + tid;
            float4 f = srow[i];
            if (f.x > cutf) { int p = atomicAdd(&sCnt, 1); if (p < CAP) cand[p] = f2s(f.x); }
            if (f.y > cutf) { int p = atomicAdd(&sCnt, 1); if (p < CAP) cand[p] = f2s(f.y); }
            if (f.z > cutf) { int p = atomicAdd(&sCnt, 1); if (p < CAP) cand[p] = f2s(f.z); }
            if (f.w > cutf) { int p = atomicAdd(&sCnt, 1); if (p < CAP) cand[p] = f2s(f.w); }
        }
        __syncthreads();
        cnt = min(sCnt, CAP);
    }

    // ---- Phase 2: exact K-th largest among candidates (4x8-bit radix select
    //      on sortable bits — bit-identical to the round-1 passing code) ----
    float Tf;
    int eqAllow;
    if (cnt <= KSEL) {
        // <= K positive values exist: all candidates win; rest ReLU to 0.
        Tf = 0.0f; eqAllow = 0;              // winners are f > 0.0f
    } else {
#pragma unroll
        for (int pass = 0; pass < 4; pass++) {
            const int shift = 24 - 8 * pass;
            const uint32_t pmask = (pass == 0) ? 0u : (0xFFFFFFFFu << (shift + 8));
            if (tid < 256) hist[tid] = 0;
            __syncthreads();
            const uint32_t prefix = sPrefix;
            const int kth = sKth;
            for (int i = tid; i < cnt; i += NT) {
                uint32_t u = cand[i];
                if ((u & pmask) == prefix) atomicAdd(&hist[(u >> shift) & 0xFFu], 1);
            }
            __syncthreads();
            if (tid < 32) {                  // warp-0 suffix scan of 256 bins
                const int lane = tid;
                const int b0 = lane * 8;
                int s[9];
                s[8] = 0;
                int run = 0;
#pragma unroll
                for (int i = 7; i >= 0; i--) { run += (int)hist[b0 + i]; s[i] = run; }
                int incl = run;
#pragma unroll
                for (int off = 1; off < 32; off <<= 1) {
                    int v = __shfl_down_sync(0xFFFFFFFFu, incl, off);
                    if (lane + off < 32) incl += v;
                }
                int excl = __shfl_down_sync(0xFFFFFFFFu, incl, 1);
                if (lane == 31) excl = 0;
#pragma unroll
                for (int i = 0; i < 8; i++) {
                    int suf = s[i] + excl;       // # candidates >= this bin
                    int nxt = s[i + 1] + excl;   // # candidates strictly above
                    if (suf >= kth && nxt < kth) {
                        sPrefix = prefix | ((uint32_t)(b0 + i) << shift);
                        sKth = kth - nxt;
                    }
                }
            }
            __syncthreads();
        }
        Tf = s2f(sPrefix);                   // exact K-th largest value (> 2.0)
        eqAllow = sKth;                      // # ties at Tf to accept (>= 1)
    }

    // ---- Phase 3: full-row streaming write from SMEM; every address written
    //      exactly once (round-1 proven pattern). Float compares == sortable
    //      compares on this domain (Tf > 0, no NaNs). ----
#pragma unroll
    for (int j = 0; j < VEC; j++) {
        const int i = j * NT + tid;
        float4 f = srow[i];
        float4 o;
        o.x = (f.x > Tf) ? f.x : 0.0f;
        o.y = (f.y > Tf) ? f.y : 0.0f;
        o.z = (f.z > Tf) ? f.z : 0.0f;
        o.w = (f.w > Tf) ? f.w : 0.0f;
        if (eqAllow > 0) {                   // rare tie path (uniform predicate)
            if (f.x == Tf && atomicAdd(&sEq, 1) < eqAllow) o.x = f.x;
            if (f.y == Tf && atomicAdd(&sEq, 1) < eqAllow) o.y = f.y;
            if (f.z == Tf && atomicAdd(&sEq, 1) < eqAllow) o.z = f.z;
            if (f.w == Tf && atomicAdd(&sEq, 1) < eqAllow) o.w = f.w;
        }
        __stcs(outv + i, o);
    }
}

extern "C" void kernel_launch(void* const* d_in, const int* in_sizes, int n_in,
                              void* d_out, int out_size) {
    const float* x = (const float*)d_in[0];
    float* out = (float*)d_out;
    int rows = in_sizes[0] / COLS;

    cudaFuncSetAttribute(topk_relu_scatter,
                         cudaFuncAttributeMaxDynamicSharedMemorySize, SMEM_BYTES);
    topk_relu_scatter<<<rows, NT, SMEM_BYTES>>>(x, out);
}

// round 5
// speedup vs baseline: 1.7044x; 1.4054x over previous
#include <cuda_runtime.h>
#include <cstdint>

#define COLS   24576
#define KSEL   64
#define NT     512
#define VEC    (COLS / 4 / NT)     // 12 float4 per thread
#define CAP    3840                // candidate capacity (expected ~560 at cut=2.0)
#define SMEM_BYTES ((CAP + 256) * 4)   // 16.4 KB -> 4 CTAs/SM

// Monotonic float -> uint32 mapping (order-preserving), candidates only.
__device__ __forceinline__ uint32_t f2s(float f) {
    uint32_t b = __float_as_uint(f);
    return (b & 0x80000000u) ? ~b : (b | 0x80000000u);
}
__device__ __forceinline__ float s2f(uint32_t u) {
    uint32_t b = (u & 0x80000000u) ? (u ^ 0x80000000u) : ~u;
    return __uint_as_float(b);
}

__global__ __launch_bounds__(NT, 4)
void topk_relu_scatter(const float* __restrict__ x, float* __restrict__ out) {
    extern __shared__ uint32_t smem[];
    uint32_t* cand = smem;                    // CAP sortable candidate bits
    uint32_t* hist = smem + CAP;              // 256-bin radix histogram
    __shared__ int sCnt, sKth, sEq;
    __shared__ uint32_t sPrefix;

    const int tid = threadIdx.x;
    const long long row = blockIdx.x;

    if (tid == 0) { sCnt = 0; sEq = 0; sKth = KSEL; sPrefix = 0u; }
    __syncthreads();

    const float4* __restrict__ rowv = (const float4*)(x + row * (long long)COLS);
    float4* __restrict__ outv = (float4*)(out + row * (long long)COLS);

    // ---- Phase 1: stream row through L2 (default policy -> stays resident),
    //               rare-path candidate push. No SMEM caching of the row. ----
    float cutf = 2.0f;
#pragma unroll 4
    for (int j = 0; j < VEC; j++) {
        const int i = j * NT + tid;
        float4 f = rowv[i];
        if (f.x > cutf) { int p = atomicAdd(&sCnt, 1); if (p < CAP) cand[p] = f2s(f.x); }
        if (f.y > cutf) { int p = atomicAdd(&sCnt, 1); if (p < CAP) cand[p] = f2s(f.y); }
        if (f.z > cutf) { int p = atomicAdd(&sCnt, 1); if (p < CAP) cand[p] = f2s(f.z); }
        if (f.w > cutf) { int p = atomicAdd(&sCnt, 1); if (p < CAP) cand[p] = f2s(f.w); }
    }
    __syncthreads();
    int cnt = sCnt;

    // ---- Robustness fallback (never taken for N(0,1) rows; re-read = L2 hits) ----
    if (cnt > CAP || cnt < KSEL) {
        cutf = (cnt < KSEL) ? 0.0f : 3.0f;   // ReLU makes cut=0.0 fully general
        __syncthreads();
        if (tid == 0) sCnt = 0;
        __syncthreads();
        for (int j = 0; j < VEC; j++) {
            const int i = j * NT + tid;
            float4 f = rowv[i];
            if (f.x > cutf) { int p = atomicAdd(&sCnt, 1); if (p < CAP) cand[p] = f2s(f.x); }
            if (f.y > cutf) { int p = atomicAdd(&sCnt, 1); if (p < CAP) cand[p] = f2s(f.y); }
            if (f.z > cutf) { int p = atomicAdd(&sCnt, 1); if (p < CAP) cand[p] = f2s(f.z); }
            if (f.w > cutf) { int p = atomicAdd(&sCnt, 1); if (p < CAP) cand[p] = f2s(f.w); }
        }
        __syncthreads();
        cnt = min(sCnt, CAP);
    }

    // ---- Phase 2: exact K-th largest among candidates (4x8-bit radix select,
    //      verbatim from the passing round-4 kernel) ----
    float Tf;
    int eqAllow;
    if (cnt <= KSEL) {
        Tf = 0.0f; eqAllow = 0;              // all positives win; rest ReLU to 0
    } else {
#pragma unroll
        for (int pass = 0; pass < 4; pass++) {
            const int shift = 24 - 8 * pass;
            const uint32_t pmask = (pass == 0) ? 0u : (0xFFFFFFFFu << (shift + 8));
            if (tid < 256) hist[tid] = 0;
            __syncthreads();
            const uint32_t prefix = sPrefix;
            const int kth = sKth;
            for (int i = tid; i < cnt; i += NT) {
                uint32_t u = cand[i];
                if ((u & pmask) == prefix) atomicAdd(&hist[(u >> shift) & 0xFFu], 1);
            }
            __syncthreads();
            if (tid < 32) {                  // warp-0 suffix scan of 256 bins
                const int lane = tid;
                const int b0 = lane * 8;
                int s[9];
                s[8] = 0;
                int run = 0;
#pragma unroll
                for (int i = 7; i >= 0; i--) { run += (int)hist[b0 + i]; s[i] = run; }
                int incl = run;
#pragma unroll
                for (int off = 1; off < 32; off <<= 1) {
                    int v = __shfl_down_sync(0xFFFFFFFFu, incl, off);
                    if (lane + off < 32) incl += v;
                }
                int excl = __shfl_down_sync(0xFFFFFFFFu, incl, 1);
                if (lane == 31) excl = 0;
#pragma unroll
                for (int i = 0; i < 8; i++) {
                    int suf = s[i] + excl;       // # candidates >= this bin
                    int nxt = s[i + 1] + excl;   // # candidates strictly above
                    if (suf >= kth && nxt < kth) {
                        sPrefix = prefix | ((uint32_t)(b0 + i) << shift);
                        sKth = kth - nxt;
                    }
                }
            }
            __syncthreads();
        }
        Tf = s2f(sPrefix);                   // exact K-th largest value (> 2.0)
        eqAllow = sKth;                      // # ties at Tf to accept (>= 1)
    }

    // ---- Phase 3: re-read row (L2 hits), write every address exactly once.
    //      Float compares == sortable compares on this domain (Tf >= 0, no NaNs). ----
#pragma unroll 4
    for (int j = 0; j < VEC; j++) {
        const int i = j * NT + tid;
        float4 f = __ldcs(rowv + i);         // done with this data: evict-first
        float4 o;
        o.x = (f.x > Tf) ? f.x : 0.0f;
        o.y = (f.y > Tf) ? f.y : 0.0f;
        o.z = (f.z > Tf) ? f.z : 0.0f;
        o.w = (f.w > Tf) ? f.w : 0.0f;
        if (eqAllow > 0) {                   // rare tie path (uniform predicate)
            if (f.x == Tf && atomicAdd(&sEq, 1) < eqAllow) o.x = f.x;
            if (f.y == Tf && atomicAdd(&sEq, 1) < eqAllow) o.y = f.y;
            if (f.z == Tf && atomicAdd(&sEq, 1) < eqAllow) o.z = f.z;
            if (f.w == Tf && atomicAdd(&sEq, 1) < eqAllow) o.w = f.w;
        }
        __stcs(outv + i, o);
    }
}

extern "C" void kernel_launch(void* const* d_in, const int* in_sizes, int n_in,
                              void* d_out, int out_size) {
    const float* x = (const float*)d_in[0];
    float* out = (float*)d_out;
    int rows = in_sizes[0] / COLS;

    cudaFuncSetAttribute(topk_relu_scatter,
                         cudaFuncAttributeMaxDynamicSharedMemorySize, SMEM_BYTES);
    topk_relu_scatter<<<rows, NT, SMEM_BYTES>>>(x, out);
}